// round 9
// baseline (speedup 1.0000x reference)
#include <cuda_runtime.h>
#include <math.h>

#define N_NODES 50000
#define N_EDGES 800000
#define NHEADS  8
#define MULT    16

// Scratch (device globals — no allocation allowed)
__device__ float g_e[(size_t)N_EDGES * NHEADS];   // exp scores (25.6 MB)
__device__ float g_s[(size_t)N_NODES * NHEADS];   // softmax denominators (1.6 MB)

// ---------------------------------------------------------------------------
// Pass 1: one (edge, head) per slot, TWO slots per thread at stride total/2.
// New in R8:
//   - zeroes d_out (1 float/thread, coalesced) -> kills the 12.8MB memset
//   - denominator atomics paired via shuffle: even lane issues red.v2 for
//     heads {h, h+1} of its edge -> halves REDG lanes (6.4M -> 3.2M)
// Grid is exact (3.2M threads), no bounds check -> shuffles safe.
// ---------------------------------------------------------------------------
__global__ void __launch_bounds__(256) pass1_scores(
    const float* __restrict__ k0, const float* __restrict__ k1,
    const float* __restrict__ q0, const float* __restrict__ q1,
    const int* __restrict__ row_idx, const int* __restrict__ col_idx,
    float* __restrict__ out_zero)
{
    const int HALF = N_EDGES * NHEADS / 2;   // 3.2M
    int t = blockIdx.x * blockDim.x + threadIdx.x;

    out_zero[t] = 0.0f;   // d_out has exactly HALF floats (50000*64 = 3.2M)

    int tA = t;
    int tB = t + HALF;
    int eA = tA >> 3, hA = tA & 7;
    int eB = tB >> 3, hB = tB & 7;   // hB == hA

    int colA = __ldg(col_idx + eA);
    int colB = __ldg(col_idx + eB);
    int rwA  = __ldg(row_idx + eA);
    int rwB  = __ldg(row_idx + eB);

    float2 kaA = *(const float2*)(k0 + (size_t)eA   * 16 + 2 * hA);
    float2 kaB = *(const float2*)(k0 + (size_t)eB   * 16 + 2 * hB);
    float2 qaA = *(const float2*)(q0 + (size_t)colA * 16 + 2 * hA);
    float2 qaB = *(const float2*)(q0 + (size_t)colB * 16 + 2 * hB);

    const float2* k1A = (const float2*)(k1 + (size_t)eA   * 48 + 6 * hA);
    const float2* q1A = (const float2*)(q1 + (size_t)colA * 48 + 6 * hA);
    const float2* k1B = (const float2*)(k1 + (size_t)eB   * 48 + 6 * hB);
    const float2* q1B = (const float2*)(q1 + (size_t)colB * 48 + 6 * hB);

    float2 kA0 = k1A[0], kA1 = k1A[1], kA2 = k1A[2];
    float2 qA0 = q1A[0], qA1 = q1A[1], qA2 = q1A[2];
    float2 kB0 = k1B[0], kB1 = k1B[1], kB2 = k1B[2];
    float2 qB0 = q1B[0], qB1 = q1B[1], qB2 = q1B[2];

    float dA = kaA.x * qaA.x + kaA.y * qaA.y
             + kA0.x * qA0.x + kA0.y * qA0.y
             + kA1.x * qA1.x + kA1.y * qA1.y
             + kA2.x * qA2.x + kA2.y * qA2.y;
    float dB = kaB.x * qaB.x + kaB.y * qaB.y
             + kB0.x * qB0.x + kB0.y * qB0.y
             + kB1.x * qB1.x + kB1.y * qB1.y
             + kB2.x * qB2.x + kB2.y * qB2.y;

    float wA = expf(dA * 0.125f);   // 1/sqrt(64)
    float wB = expf(dB * 0.125f);

    g_e[tA] = wA;
    g_e[tB] = wB;

    // Pair heads {h, h+1} (same edge, same row) across lane pairs:
    // odd lane passes its w down; even lane issues one red.v2 per slot.
    float wA_hi = __shfl_down_sync(0xFFFFFFFFu, wA, 1);
    float wB_hi = __shfl_down_sync(0xFFFFFFFFu, wB, 1);
    if ((hA & 1) == 0) {
        float* pA = g_s + (size_t)rwA * NHEADS + hA;   // 8B aligned (h even)
        float* pB = g_s + (size_t)rwB * NHEADS + hB;
        asm volatile("red.global.add.v2.f32 [%0], {%1, %2};"
                     :: "l"(pA), "f"(wA), "f"(wA_hi) : "memory");
        asm volatile("red.global.add.v2.f32 [%0], {%1, %2};"
                     :: "l"(pB), "f"(wB), "f"(wB_hi) : "memory");
    }
}

// ---------------------------------------------------------------------------
// Quad-shuffle: lane r of the 4-lane quad holds a0=a[2r], a1=a[2r+1].
// ---------------------------------------------------------------------------
__device__ __forceinline__ float quad_a(float a0, float a1, int h)
{
    float s0 = __shfl_sync(0xFFFFFFFFu, a0, h >> 1, 4);
    float s1 = __shfl_sync(0xFFFFFFFFu, a1, h >> 1, 4);
    return (h & 1) ? s1 : s0;
}

// ---------------------------------------------------------------------------
// Pass 2 (R7 winner, unchanged): FOUR threads per edge, interleaved out1
// chunks {q, 4+q, 8+q} -> every RED instruction covers one contiguous 64B
// piece per edge (full L2 sector merging). Fused MUFU reciprocal.
// ---------------------------------------------------------------------------
__global__ void __launch_bounds__(256) pass2_scatter(
    const float* __restrict__ v0, const float* __restrict__ v1,
    const int* __restrict__ row_idx, const int* __restrict__ col_idx,
    float* __restrict__ out0, float* __restrict__ out1)
{
    int t = blockIdx.x * blockDim.x + threadIdx.x;
    int e = t >> 2;
    int q = t & 3;

    int rw  = __ldg(row_idx + e);
    int col = __ldg(col_idx + e);

    float2 ew = *(const float2*)(g_e + (size_t)e  * NHEADS + 2 * q);
    float2 sw = *(const float2*)(g_s + (size_t)rw * NHEADS + 2 * q);
    float a0 = ew.x * __fdividef(1.0f, sw.x);
    float a1 = ew.y * __fdividef(1.0f, sw.y);

    {
        float4 v = __ldg((const float4*)(v0 + (size_t)e * 16 + 4 * q));
        float* p = out0 + (size_t)col * 16 + 4 * q;
        asm volatile("red.global.add.v4.f32 [%0], {%1, %2, %3, %4};"
                     :: "l"(p), "f"(v.x * a0), "f"(v.y * a0),
                        "f"(v.z * a1), "f"(v.w * a1) : "memory");
    }

    const float4* vp = (const float4*)(v1 + (size_t)e * 48);
    float* p = out1 + (size_t)col * 48;

#pragma unroll
    for (int j = 0; j < 3; j++) {
        int c = 4 * j + q;
        float4 v = __ldg(vp + c);
        int hlo = (2 * c) / 3;
        int hhi = hlo + ((c % 3) == 1 ? 1 : 0);
        float mlo = quad_a(a0, a1, hlo);
        float mhi = quad_a(a0, a1, hhi);
        asm volatile("red.global.add.v4.f32 [%0], {%1, %2, %3, %4};"
                     :: "l"(p + 4 * c), "f"(v.x * mlo), "f"(v.y * mlo),
                        "f"(v.z * mhi), "f"(v.w * mhi) : "memory");
    }
}

// ---------------------------------------------------------------------------
// Launch.  Inputs: v0, v1, k0, k1, q0, q1, edge_index
// Output: out0 (N*16) ++ out1 (N*48)
// ---------------------------------------------------------------------------
extern "C" void kernel_launch(void* const* d_in, const int* in_sizes, int n_in,
                              void* d_out, int out_size)
{
    const float* v0 = (const float*)d_in[0];
    const float* v1 = (const float*)d_in[1];
    const float* k0 = (const float*)d_in[2];
    const float* k1 = (const float*)d_in[3];
    const float* q0 = (const float*)d_in[4];
    const float* q1 = (const float*)d_in[5];
    const int*   ei = (const int*)  d_in[6];
    const int* row_idx = ei;             // edge_index[0]
    const int* col_idx = ei + N_EDGES;   // edge_index[1]

    float* out0 = (float*)d_out;
    float* out1 = out0 + (size_t)N_NODES * MULT;

    void* s_addr = nullptr;
    cudaGetSymbolAddress(&s_addr, g_s);

    cudaMemsetAsync(s_addr, 0, (size_t)N_NODES * NHEADS * sizeof(float));
    // d_out zeroing folded into pass1 (out_size == N_EDGES*NHEADS/2 floats)

    int half = N_EDGES * NHEADS / 2;      // 3.2M, divides 256 exactly
    pass1_scores<<<half / 256, 256>>>(k0, k1, q0, q1, row_idx, col_idx,
                                      (float*)d_out);

    int n2 = N_EDGES * 4;                 // 3.2M, divides 256 exactly
    pass2_scatter<<<n2 / 256, 256>>>(v0, v1, row_idx, col_idx, out0, out1);
}